// round 1
// baseline (speedup 1.0000x reference)
#include <cuda_runtime.h>
#include <math.h>

#define H 64
#define HNUM 256
#define NMAX 100000
#define EMAX 1200000
#define NEG_SLOPE 0.2f

// ---------------- scratch (static device globals; no allocation) ----------------
__device__ float g_h[(size_t)NMAX * H];       // GAT input features per layer
__device__ float g_out[(size_t)NMAX * H];     // GAT output per layer
__device__ float g_as[NMAX];                  // per-node src attention scalar
__device__ float g_ad[NMAX];                  // per-node dst attention scalar
__device__ int   g_deg[NMAX + 1];
__device__ int   g_offs[NMAX + 1];
__device__ int   g_cur[NMAX + 1];
__device__ int   g_ssrc[EMAX + NMAX];         // src node per dst-sorted edge slot
__device__ float g_vn[(HNUM + 1) * H];        // rows 0..255 = vn_direct, row 256 = vn_root
__device__ float g_vntmp[HNUM * H];           // segment_sum scratch
__device__ float g_wain[6];                   // input layer: x@(W a_src) coeffs (3 src, 3 dst)
__device__ float g_uv[4 * H];                 // hidden layers: W@a_src / W@a_dst per layer

// ---------------- small prep: fold attention vectors through W ----------------
__global__ void k_prep(const float* __restrict__ w_in,
                       const float* __restrict__ a_src_in,
                       const float* __restrict__ a_dst_in,
                       const float* __restrict__ w_l,
                       const float* __restrict__ a_src_l,
                       const float* __restrict__ a_dst_l,
                       float* __restrict__ wa_in, float* __restrict__ uv) {
    int t = threadIdx.x;               // 256 threads
    int l = t >> 7;                    // 0/1
    int isdst = (t >> 6) & 1;
    int j = t & 63;
    const float* a = isdst ? (a_dst_l + l * H) : (a_src_l + l * H);
    const float* W = w_l + l * H * H;
    float s = 0.f;
    #pragma unroll 8
    for (int k = 0; k < H; k++) s += W[j * H + k] * a[k];
    uv[(l * 2 + isdst) * H + j] = s;
    if (t < 6) {
        int i = t % 3;
        const float* av = (t >= 3) ? a_dst_in : a_src_in;
        float s2 = 0.f;
        #pragma unroll 8
        for (int k = 0; k < H; k++) s2 += w_in[i * H + k] * av[k];
        wa_in[t] = s2;
    }
}

// ---------------- CSR build ----------------
__global__ void k_initdeg(int* deg, int n) {
    int i = blockIdx.x * blockDim.x + threadIdx.x;
    if (i < n) deg[i] = 1;   // self loop
}

__global__ void k_hist(const int* __restrict__ ei, int* deg, int E) {
    int i = blockIdx.x * blockDim.x + threadIdx.x;
    if (i < E) atomicAdd(&deg[ei[E + i]], 1);
}

// single-block exclusive scan over n (<=NMAX) elements, 1024 threads
__global__ void k_scan(const int* __restrict__ deg, int* __restrict__ offs,
                       int* __restrict__ cur, int n) {
    __shared__ int sWarp[32];
    __shared__ int sCarry;
    int t = threadIdx.x, lane = t & 31, wid = t >> 5;
    if (t == 0) sCarry = 0;
    __syncthreads();
    for (int base = 0; base < n; base += 1024) {
        int i = base + t;
        int v = (i < n) ? deg[i] : 0;
        int x = v;
        #pragma unroll
        for (int d = 1; d < 32; d <<= 1) {
            int y = __shfl_up_sync(0xffffffffu, x, d);
            if (lane >= d) x += y;
        }
        if (lane == 31) sWarp[wid] = x;
        __syncthreads();
        if (wid == 0) {
            int s = sWarp[lane];
            #pragma unroll
            for (int d = 1; d < 32; d <<= 1) {
                int y = __shfl_up_sync(0xffffffffu, s, d);
                if (lane >= d) s += y;
            }
            sWarp[lane] = s;
        }
        __syncthreads();
        int pre = (wid > 0 ? sWarp[wid - 1] : 0) + sCarry;
        int incl = x + pre;
        if (i < n) { offs[i] = incl - v; cur[i] = incl - v; }
        __syncthreads();
        if (t == 1023) sCarry = incl;
        __syncthreads();
    }
    if (t == 0) offs[n] = sCarry;
}

__global__ void k_scatter(const int* __restrict__ ei, int* cur,
                          int* __restrict__ ssrc, int E, int n) {
    int i = blockIdx.x * blockDim.x + threadIdx.x;
    int total = E + n;
    if (i >= total) return;
    int s, d;
    if (i < E) { s = ei[i]; d = ei[E + i]; }
    else       { s = i - E; d = s; }
    int pos = atomicAdd(&cur[d], 1);
    ssrc[pos] = s;
}

// ---------------- misc small kernels ----------------
__global__ void k_vninit(float* vn, const float* __restrict__ emb) {
    int i = blockIdx.x * blockDim.x + threadIdx.x;
    if (i < (HNUM + 1) * H) vn[i] = emb[i & (H - 1)];
}

__global__ void k_zero(float* p, int n) {
    int i = blockIdx.x * blockDim.x + threadIdx.x;
    if (i < n) p[i] = 0.f;
}

// ---------------- input transform: h = x@W_in, as/ad = x@wa ----------------
__global__ void k_input_transform(const float* __restrict__ x,
                                  const float* __restrict__ w_in,
                                  const float* __restrict__ wa,
                                  float* __restrict__ h,
                                  float* __restrict__ as_, float* __restrict__ ad_,
                                  int n) {
    __shared__ float sW[3 * H];
    __shared__ float swa[6];
    int t = threadIdx.x;
    if (t < 3 * H) sW[t] = w_in[t];
    if (t < 6) swa[t] = wa[t];
    __syncthreads();
    int warp = (blockIdx.x * blockDim.x + t) >> 5;
    int lane = t & 31;
    if (warp >= n) return;
    float x0 = x[warp * 3 + 0], x1 = x[warp * 3 + 1], x2 = x[warp * 3 + 2];
    float ha = x0 * sW[lane]      + x1 * sW[H + lane]      + x2 * sW[2 * H + lane];
    float hb = x0 * sW[32 + lane] + x1 * sW[H + 32 + lane] + x2 * sW[2 * H + 32 + lane];
    h[(size_t)warp * H + lane]      = ha;
    h[(size_t)warp * H + lane + 32] = hb;
    if (lane == 0) {
        as_[warp] = x0 * swa[0] + x1 * swa[1] + x2 * swa[2];
        ad_[warp] = x0 * swa[3] + x1 * swa[4] + x2 * swa[5];
    }
}

// ---------------- hidden-layer GEMM: Hout = (A + vn[hb]) @ W, plus as/ad ----------------
__global__ __launch_bounds__(256) void k_gemm64(
    const float* __restrict__ A, const float* __restrict__ W,
    const float* __restrict__ u, const float* __restrict__ v,
    const float* __restrict__ vn, const int* __restrict__ hb,
    float* __restrict__ Hout, float* __restrict__ as_, float* __restrict__ ad_,
    int n) {
    __shared__ __align__(16) float sW[H * H];
    __shared__ float sA[64 * 65];
    int t = threadIdx.x;
    for (int i = t; i < H * H; i += 256) sW[i] = W[i];
    int block_row = blockIdx.x * 64;
    for (int i = t; i < 64 * H; i += 256) {
        int r = i >> 6, c = i & 63;
        int node = block_row + r;
        float val = 0.f;
        if (node < n) {
            val = A[(size_t)node * H + c] + vn[hb[node] * H + c];
        }
        sA[r * 65 + c] = val;
    }
    __syncthreads();
    int ty = t >> 4, tx = t & 15;
    float acc[4][4] = {};
    #pragma unroll 8
    for (int k = 0; k < H; k++) {
        float a0 = sA[(ty * 4 + 0) * 65 + k];
        float a1 = sA[(ty * 4 + 1) * 65 + k];
        float a2 = sA[(ty * 4 + 2) * 65 + k];
        float a3 = sA[(ty * 4 + 3) * 65 + k];
        float4 w4 = *(const float4*)&sW[k * H + tx * 4];
        acc[0][0] += a0 * w4.x; acc[0][1] += a0 * w4.y; acc[0][2] += a0 * w4.z; acc[0][3] += a0 * w4.w;
        acc[1][0] += a1 * w4.x; acc[1][1] += a1 * w4.y; acc[1][2] += a1 * w4.z; acc[1][3] += a1 * w4.w;
        acc[2][0] += a2 * w4.x; acc[2][1] += a2 * w4.y; acc[2][2] += a2 * w4.z; acc[2][3] += a2 * w4.w;
        acc[3][0] += a3 * w4.x; acc[3][1] += a3 * w4.y; acc[3][2] += a3 * w4.z; acc[3][3] += a3 * w4.w;
    }
    #pragma unroll
    for (int i = 0; i < 4; i++) {
        int node = block_row + ty * 4 + i;
        if (node < n) {
            #pragma unroll
            for (int j = 0; j < 4; j++)
                Hout[(size_t)node * H + tx * 4 + j] = acc[i][j];
        }
    }
    // as/ad from the same A tile
    if (t < 64) {
        int node = block_row + t;
        if (node < n) {
            float s = 0.f, d = 0.f;
            #pragma unroll 8
            for (int k = 0; k < H; k++) {
                float a = sA[t * 65 + k];
                s += a * u[k];
                d += a * v[k];
            }
            as_[node] = s;
            ad_[node] = d;
        }
    }
}

// ---------------- GAT softmax + aggregation, one warp per dst node ----------------
__global__ __launch_bounds__(256) void k_gat_aggregate(
    const float* __restrict__ h,
    const float* __restrict__ as_, const float* __restrict__ ad_,
    const int* __restrict__ offs, const int* __restrict__ ssrc,
    const float* __restrict__ bias,
    float* __restrict__ out, int n) {
    int warp = (blockIdx.x * blockDim.x + threadIdx.x) >> 5;
    int lane = threadIdx.x & 31;
    if (warp >= n) return;
    int start = offs[warp], end = offs[warp + 1];
    float adn = ad_[warp];

    // pass 1: max over incoming edges
    float m = -INFINITY;
    for (int e = start + lane; e < end; e += 32) {
        float a = as_[ssrc[e]] + adn;
        a = a > 0.f ? a : NEG_SLOPE * a;
        m = fmaxf(m, a);
    }
    #pragma unroll
    for (int o = 16; o; o >>= 1) m = fmaxf(m, __shfl_xor_sync(0xffffffffu, m, o));

    // pass 2: exp weights + fused weighted feature accumulation
    float acc0 = 0.f, acc1 = 0.f, den = 0.f;
    for (int eb = start; eb < end; eb += 32) {
        int e = eb + lane;
        float ex = 0.f; int s = 0;
        if (e < end) {
            s = ssrc[e];
            float a = as_[s] + adn;
            a = a > 0.f ? a : NEG_SLOPE * a;
            ex = __expf(a - m);
        }
        den += ex;
        int cnt = min(32, end - eb);
        for (int j = 0; j < cnt; j++) {
            float w = __shfl_sync(0xffffffffu, ex, j);
            int sj  = __shfl_sync(0xffffffffu, s, j);
            const float* hp = h + (size_t)sj * H;
            acc0 += w * hp[lane];
            acc1 += w * hp[lane + 32];
        }
    }
    #pragma unroll
    for (int o = 16; o; o >>= 1) den += __shfl_xor_sync(0xffffffffu, den, o);
    float inv = 1.f / den;
    out[(size_t)warp * H + lane]      = acc0 * inv + bias[lane];
    out[(size_t)warp * H + lane + 32] = acc1 * inv + bias[lane + 32];
}

// ---------------- virtual-node segment sum (atomic into 256x64) ----------------
__global__ void k_vn_segsum(const float* __restrict__ out, const int* __restrict__ hb,
                            float* vn_tmp, int n) {
    int warp = (blockIdx.x * blockDim.x + threadIdx.x) >> 5;
    int lane = threadIdx.x & 31;
    if (warp >= n) return;
    int b = hb[warp];
    atomicAdd(&vn_tmp[b * H + lane],      out[(size_t)warp * H + lane]);
    atomicAdd(&vn_tmp[b * H + lane + 32], out[(size_t)warp * H + lane + 32]);
}

// ---------------- vn update: direct += seg + root; root += colsum(direct) ----------------
__global__ void k_vn_update(float* vn, const float* __restrict__ vn_tmp) {
    int t = threadIdx.x;  // 256
    for (int i = t; i < HNUM * H; i += 256) {
        vn[i] = vn[i] + vn_tmp[i] + vn[HNUM * H + (i & (H - 1))];
    }
    __syncthreads();
    if (t < H) {
        float s = 0.f;
        for (int r = 0; r < HNUM; r++) s += vn[r * H + t];
        vn[HNUM * H + t] += s;
    }
}

// ---------------- fused 2-layer MLP with ReLUs on vn rows (in place) ----------------
__global__ __launch_bounds__(256) void k_mlp_fused(
    float* vn, const float* __restrict__ w1, const float* __restrict__ b1,
    const float* __restrict__ w2, const float* __restrict__ b2, int rows) {
    __shared__ __align__(16) float sW[H * H];
    __shared__ float sV[64 * 65];
    int t = threadIdx.x;
    for (int i = t; i < H * H; i += 256) sW[i] = w1[i];
    int r0 = blockIdx.x * 64;
    for (int i = t; i < 64 * H; i += 256) {
        int r = i >> 6, c = i & 63;
        sV[r * 65 + c] = (r0 + r < rows) ? vn[(r0 + r) * H + c] : 0.f;
    }
    __syncthreads();
    int ty = t >> 4, tx = t & 15;
    float acc[4][4] = {};
    #pragma unroll 8
    for (int k = 0; k < H; k++) {
        float a0 = sV[(ty * 4 + 0) * 65 + k];
        float a1 = sV[(ty * 4 + 1) * 65 + k];
        float a2 = sV[(ty * 4 + 2) * 65 + k];
        float a3 = sV[(ty * 4 + 3) * 65 + k];
        float4 w4 = *(const float4*)&sW[k * H + tx * 4];
        acc[0][0] += a0 * w4.x; acc[0][1] += a0 * w4.y; acc[0][2] += a0 * w4.z; acc[0][3] += a0 * w4.w;
        acc[1][0] += a1 * w4.x; acc[1][1] += a1 * w4.y; acc[1][2] += a1 * w4.z; acc[1][3] += a1 * w4.w;
        acc[2][0] += a2 * w4.x; acc[2][1] += a2 * w4.y; acc[2][2] += a2 * w4.z; acc[2][3] += a2 * w4.w;
        acc[3][0] += a3 * w4.x; acc[3][1] += a3 * w4.y; acc[3][2] += a3 * w4.z; acc[3][3] += a3 * w4.w;
    }
    __syncthreads();  // all reads of sV / sW(w1) done
    // T = relu(acc + b1) -> sV ; w2 -> sW
    #pragma unroll
    for (int i = 0; i < 4; i++) {
        #pragma unroll
        for (int j = 0; j < 4; j++) {
            float vbl = acc[i][j] + b1[tx * 4 + j];
            sV[(ty * 4 + i) * 65 + tx * 4 + j] = vbl > 0.f ? vbl : 0.f;
        }
    }
    for (int i = t; i < H * H; i += 256) sW[i] = w2[i];
    __syncthreads();
    float acc2[4][4] = {};
    #pragma unroll 8
    for (int k = 0; k < H; k++) {
        float a0 = sV[(ty * 4 + 0) * 65 + k];
        float a1 = sV[(ty * 4 + 1) * 65 + k];
        float a2 = sV[(ty * 4 + 2) * 65 + k];
        float a3 = sV[(ty * 4 + 3) * 65 + k];
        float4 w4 = *(const float4*)&sW[k * H + tx * 4];
        acc2[0][0] += a0 * w4.x; acc2[0][1] += a0 * w4.y; acc2[0][2] += a0 * w4.z; acc2[0][3] += a0 * w4.w;
        acc2[1][0] += a1 * w4.x; acc2[1][1] += a1 * w4.y; acc2[1][2] += a1 * w4.z; acc2[1][3] += a1 * w4.w;
        acc2[2][0] += a2 * w4.x; acc2[2][1] += a2 * w4.y; acc2[2][2] += a2 * w4.z; acc2[2][3] += a2 * w4.w;
        acc2[3][0] += a3 * w4.x; acc2[3][1] += a3 * w4.y; acc2[3][2] += a3 * w4.z; acc2[3][3] += a3 * w4.w;
    }
    #pragma unroll
    for (int i = 0; i < 4; i++) {
        int r = r0 + ty * 4 + i;
        if (r < rows) {
            #pragma unroll
            for (int j = 0; j < 4; j++) {
                float vbl = acc2[i][j] + b2[tx * 4 + j];
                vn[r * H + tx * 4 + j] = vbl > 0.f ? vbl : 0.f;
            }
        }
    }
}

// ---------------- host launch ----------------
extern "C" void kernel_launch(void* const* d_in, const int* in_sizes, int n_in,
                              void* d_out, int out_size) {
    const float* x  = (const float*)d_in[0];
    const int*   ei = (const int*)d_in[1];
    const int*   hb = (const int*)d_in[2];
    // d_in[3] = h_levels (unused). h_num may or may not be materialized as an input.
    int base = (n_in >= 18) ? 5 : 4;
    const float* w_in     = (const float*)d_in[base + 0];
    const float* a_src_in = (const float*)d_in[base + 1];
    const float* a_dst_in = (const float*)d_in[base + 2];
    const float* b_in     = (const float*)d_in[base + 3];
    const float* w_l      = (const float*)d_in[base + 4];
    const float* a_src_l  = (const float*)d_in[base + 5];
    const float* a_dst_l  = (const float*)d_in[base + 6];
    const float* b_l      = (const float*)d_in[base + 7];
    const float* mw1      = (const float*)d_in[base + 8];
    const float* mb1      = (const float*)d_in[base + 9];
    const float* mw2      = (const float*)d_in[base + 10];
    const float* mb2      = (const float*)d_in[base + 11];
    const float* vne      = (const float*)d_in[base + 12];

    int N = in_sizes[0] / 3;
    int E = in_sizes[1] / 2;

    float *ph, *pout, *pas, *pad, *pvn, *pvntmp, *pwain, *puv;
    int *pdeg, *poffs, *pcur, *pssrc;
    cudaGetSymbolAddress((void**)&ph, g_h);
    cudaGetSymbolAddress((void**)&pout, g_out);
    cudaGetSymbolAddress((void**)&pas, g_as);
    cudaGetSymbolAddress((void**)&pad, g_ad);
    cudaGetSymbolAddress((void**)&pdeg, g_deg);
    cudaGetSymbolAddress((void**)&poffs, g_offs);
    cudaGetSymbolAddress((void**)&pcur, g_cur);
    cudaGetSymbolAddress((void**)&pssrc, g_ssrc);
    cudaGetSymbolAddress((void**)&pvn, g_vn);
    cudaGetSymbolAddress((void**)&pvntmp, g_vntmp);
    cudaGetSymbolAddress((void**)&pwain, g_wain);
    cudaGetSymbolAddress((void**)&puv, g_uv);

    int nwarp_blocks = (N + 7) / 8;          // 8 warps per 256-thread block
    int gemm_blocks  = (N + 63) / 64;

    // prep + CSR build (graph is per-launch input, rebuilt each call)
    k_prep<<<1, 256>>>(w_in, a_src_in, a_dst_in, w_l, a_src_l, a_dst_l, pwain, puv);
    k_initdeg<<<(N + 255) / 256, 256>>>(pdeg, N);
    k_hist<<<(E + 255) / 256, 256>>>(ei, pdeg, E);
    k_scan<<<1, 1024>>>(pdeg, poffs, pcur, N);
    k_scatter<<<(E + N + 255) / 256, 256>>>(ei, pcur, pssrc, E, N);
    k_vninit<<<((HNUM + 1) * H + 255) / 256, 256>>>(pvn, vne);

    // input GAT layer
    k_input_transform<<<nwarp_blocks, 256>>>(x, w_in, pwain, ph, pas, pad, N);
    k_gat_aggregate<<<nwarp_blocks, 256>>>(ph, pas, pad, poffs, pssrc, b_in, pout, N);

    // l = 0
    k_gemm64<<<gemm_blocks, 256>>>(pout, w_l, puv, puv + H, pvn, hb, ph, pas, pad, N);
    k_gat_aggregate<<<nwarp_blocks, 256>>>(ph, pas, pad, poffs, pssrc, b_l, pout, N);
    k_zero<<<(HNUM * H + 255) / 256, 256>>>(pvntmp, HNUM * H);
    k_vn_segsum<<<nwarp_blocks, 256>>>(pout, hb, pvntmp, N);
    k_vn_update<<<1, 256>>>(pvn, pvntmp);
    k_mlp_fused<<<(HNUM + 1 + 63) / 64, 256>>>(pvn, mw1, mb1, mw2, mb2, HNUM + 1);
    k_mlp_fused<<<(HNUM + 1 + 63) / 64, 256>>>(pvn, mw1 + H * H, mb1 + H,
                                               mw2 + H * H, mb2 + H, HNUM + 1);

    // l = 1 (vn updates after the last GAT never affect the output -> skipped)
    k_gemm64<<<gemm_blocks, 256>>>(pout, w_l + H * H, puv + 2 * H, puv + 3 * H,
                                   pvn, hb, ph, pas, pad, N);
    k_gat_aggregate<<<nwarp_blocks, 256>>>(ph, pas, pad, poffs, pssrc, b_l + H,
                                           (float*)d_out, N);
}

// round 2
// speedup vs baseline: 1.0991x; 1.0991x over previous
#include <cuda_runtime.h>
#include <math.h>

#define H 64
#define HNUM 256
#define NMAX 100000
#define EMAX 1200000
#define NEG_SLOPE 0.2f
#define SCAN_TILE 1024

// ---------------- scratch (static device globals; no allocation) ----------------
__device__ float g_h[(size_t)NMAX * H];       // GAT input features per layer
__device__ float g_out[(size_t)NMAX * H];     // GAT output per layer
__device__ float g_as[NMAX];                  // per-node src attention scalar
__device__ float g_ad[NMAX];                  // per-node dst attention scalar
__device__ float g_alpha[EMAX + NMAX];        // per-edge leaky-relu attention logit
__device__ int   g_deg[NMAX + 1];
__device__ int   g_offs[NMAX + 1];
__device__ int   g_cur[NMAX + 1];
__device__ int   g_bsum[256];                 // block partial sums (<=98 used)
__device__ int   g_bsum_ex[257];              // exclusive-scanned partials + total
__device__ int   g_ssrc[EMAX + NMAX];         // src node per dst-sorted edge slot
__device__ float g_vn[(HNUM + 1) * H];        // rows 0..255 = vn_direct, row 256 = vn_root
__device__ float g_vntmp[HNUM * H];           // segment_sum scratch
__device__ float g_wain[6];                   // input layer: x@(W a_src) coeffs
__device__ float g_uv[4 * H];                 // hidden layers: W@a_src / W@a_dst per layer

// ---------------- small prep: fold attention vectors through W ----------------
__global__ void k_prep(const float* __restrict__ w_in,
                       const float* __restrict__ a_src_in,
                       const float* __restrict__ a_dst_in,
                       const float* __restrict__ w_l,
                       const float* __restrict__ a_src_l,
                       const float* __restrict__ a_dst_l,
                       float* __restrict__ wa_in, float* __restrict__ uv) {
    int t = threadIdx.x;               // 256 threads
    int l = t >> 7;                    // 0/1
    int isdst = (t >> 6) & 1;
    int j = t & 63;
    const float* a = isdst ? (a_dst_l + l * H) : (a_src_l + l * H);
    const float* W = w_l + l * H * H;
    float s = 0.f;
    #pragma unroll 8
    for (int k = 0; k < H; k++) s += W[j * H + k] * a[k];
    uv[(l * 2 + isdst) * H + j] = s;
    if (t < 6) {
        int i = t % 3;
        const float* av = (t >= 3) ? a_dst_in : a_src_in;
        float s2 = 0.f;
        #pragma unroll 8
        for (int k = 0; k < H; k++) s2 += w_in[i * H + k] * av[k];
        wa_in[t] = s2;
    }
}

// ---------------- CSR build ----------------
__global__ void k_initdeg(int* deg, int n) {
    int i = blockIdx.x * blockDim.x + threadIdx.x;
    if (i < n) deg[i] = 1;   // self loop
}

__global__ void k_hist(const int* __restrict__ ei, int* deg, int E) {
    int i = blockIdx.x * blockDim.x + threadIdx.x;
    if (i < E) atomicAdd(&deg[ei[E + i]], 1);
}

// two-level scan, stage 1: per-block (1024 elems) exclusive scan + block sum
__global__ void k_scan_blk(const int* __restrict__ deg, int* __restrict__ offs,
                           int* __restrict__ bsum, int n) {
    __shared__ int sWarp[32];
    int t = threadIdx.x, lane = t & 31, wid = t >> 5;
    int i = blockIdx.x * SCAN_TILE + t;
    int v = (i < n) ? deg[i] : 0;
    int x = v;
    #pragma unroll
    for (int d = 1; d < 32; d <<= 1) {
        int y = __shfl_up_sync(0xffffffffu, x, d);
        if (lane >= d) x += y;
    }
    if (lane == 31) sWarp[wid] = x;
    __syncthreads();
    if (wid == 0) {
        int s = sWarp[lane];
        #pragma unroll
        for (int d = 1; d < 32; d <<= 1) {
            int y = __shfl_up_sync(0xffffffffu, s, d);
            if (lane >= d) s += y;
        }
        sWarp[lane] = s;
    }
    __syncthreads();
    int pre = (wid > 0 ? sWarp[wid - 1] : 0);
    int incl = x + pre;
    if (i < n) offs[i] = incl - v;           // block-local exclusive
    if (t == SCAN_TILE - 1) bsum[blockIdx.x] = incl;
}

// stage 2: single 128-thread block scans <=128 block sums -> exclusive + total
__global__ void k_scan_top(const int* __restrict__ bsum, int* __restrict__ bsum_ex,
                           int nb) {
    __shared__ int sWarp[4];
    int t = threadIdx.x, lane = t & 31, wid = t >> 5;
    int v = (t < nb) ? bsum[t] : 0;
    int x = v;
    #pragma unroll
    for (int d = 1; d < 32; d <<= 1) {
        int y = __shfl_up_sync(0xffffffffu, x, d);
        if (lane >= d) x += y;
    }
    if (lane == 31) sWarp[wid] = x;
    __syncthreads();
    int pre = 0;
    for (int w = 0; w < wid; w++) pre += sWarp[w];
    int incl = x + pre;
    if (t < nb) bsum_ex[t] = incl - v;
    if (t == nb - 1) bsum_ex[nb] = incl;     // total
}

// stage 3: add block base, write offs + cur (+ offs[n] = total)
__global__ void k_scan_add(int* __restrict__ offs, int* __restrict__ cur,
                           const int* __restrict__ bsum_ex, int n, int nb) {
    int i = blockIdx.x * SCAN_TILE + threadIdx.x;
    if (i < n) {
        int o = offs[i] + bsum_ex[blockIdx.x];
        offs[i] = o;
        cur[i] = o;
    }
    if (blockIdx.x == 0 && threadIdx.x == 0) offs[n] = bsum_ex[nb];
}

__global__ void k_scatter(const int* __restrict__ ei, int* cur,
                          int* __restrict__ ssrc, int E, int n) {
    int i = blockIdx.x * blockDim.x + threadIdx.x;
    int total = E + n;
    if (i >= total) return;
    int s, d;
    if (i < E) { s = ei[i]; d = ei[E + i]; }
    else       { s = i - E; d = s; }
    int pos = atomicAdd(&cur[d], 1);
    ssrc[pos] = s;
}

// ---------------- misc small kernels ----------------
__global__ void k_vninit(float* vn, const float* __restrict__ emb) {
    int i = blockIdx.x * blockDim.x + threadIdx.x;
    if (i < (HNUM + 1) * H) vn[i] = emb[i & (H - 1)];
}

__global__ void k_zero(float* p, int n) {
    int i = blockIdx.x * blockDim.x + threadIdx.x;
    if (i < n) p[i] = 0.f;
}

// ---------------- input transform: h = x@W_in, as/ad = x@wa ----------------
__global__ void k_input_transform(const float* __restrict__ x,
                                  const float* __restrict__ w_in,
                                  const float* __restrict__ wa,
                                  float* __restrict__ h,
                                  float* __restrict__ as_, float* __restrict__ ad_,
                                  int n) {
    __shared__ float sW[3 * H];
    __shared__ float swa[6];
    int t = threadIdx.x;
    if (t < 3 * H) sW[t] = w_in[t];
    if (t < 6) swa[t] = wa[t];
    __syncthreads();
    int warp = (blockIdx.x * blockDim.x + t) >> 5;
    int lane = t & 31;
    if (warp >= n) return;
    float x0 = x[warp * 3 + 0], x1 = x[warp * 3 + 1], x2 = x[warp * 3 + 2];
    float ha = x0 * sW[lane]      + x1 * sW[H + lane]      + x2 * sW[2 * H + lane];
    float hb = x0 * sW[32 + lane] + x1 * sW[H + 32 + lane] + x2 * sW[2 * H + 32 + lane];
    h[(size_t)warp * H + lane]      = ha;
    h[(size_t)warp * H + lane + 32] = hb;
    if (lane == 0) {
        as_[warp] = x0 * swa[0] + x1 * swa[1] + x2 * swa[2];
        ad_[warp] = x0 * swa[3] + x1 * swa[4] + x2 * swa[5];
    }
}

// ---------------- hidden-layer GEMM: Hout = (A + vn[hb]) @ W, plus as/ad ----------------
__global__ __launch_bounds__(256) void k_gemm64(
    const float* __restrict__ A, const float* __restrict__ W,
    const float* __restrict__ u, const float* __restrict__ v,
    const float* __restrict__ vn, const int* __restrict__ hb,
    float* __restrict__ Hout, float* __restrict__ as_, float* __restrict__ ad_,
    int n) {
    __shared__ __align__(16) float sW[H * H];
    __shared__ float sA[64 * 65];
    int t = threadIdx.x;
    for (int i = t; i < H * H; i += 256) sW[i] = W[i];
    int block_row = blockIdx.x * 64;
    for (int i = t; i < 64 * H; i += 256) {
        int r = i >> 6, c = i & 63;
        int node = block_row + r;
        float val = 0.f;
        if (node < n) {
            val = A[(size_t)node * H + c] + vn[hb[node] * H + c];
        }
        sA[r * 65 + c] = val;
    }
    __syncthreads();
    int ty = t >> 4, tx = t & 15;
    float acc[4][4] = {};
    #pragma unroll 8
    for (int k = 0; k < H; k++) {
        float a0 = sA[(ty * 4 + 0) * 65 + k];
        float a1 = sA[(ty * 4 + 1) * 65 + k];
        float a2 = sA[(ty * 4 + 2) * 65 + k];
        float a3 = sA[(ty * 4 + 3) * 65 + k];
        float4 w4 = *(const float4*)&sW[k * H + tx * 4];
        acc[0][0] += a0 * w4.x; acc[0][1] += a0 * w4.y; acc[0][2] += a0 * w4.z; acc[0][3] += a0 * w4.w;
        acc[1][0] += a1 * w4.x; acc[1][1] += a1 * w4.y; acc[1][2] += a1 * w4.z; acc[1][3] += a1 * w4.w;
        acc[2][0] += a2 * w4.x; acc[2][1] += a2 * w4.y; acc[2][2] += a2 * w4.z; acc[2][3] += a2 * w4.w;
        acc[3][0] += a3 * w4.x; acc[3][1] += a3 * w4.y; acc[3][2] += a3 * w4.z; acc[3][3] += a3 * w4.w;
    }
    #pragma unroll
    for (int i = 0; i < 4; i++) {
        int node = block_row + ty * 4 + i;
        if (node < n) {
            #pragma unroll
            for (int j = 0; j < 4; j++)
                Hout[(size_t)node * H + tx * 4 + j] = acc[i][j];
        }
    }
    // as/ad from the same A tile
    if (t < 64) {
        int node = block_row + t;
        if (node < n) {
            float s = 0.f, d = 0.f;
            #pragma unroll 8
            for (int k = 0; k < H; k++) {
                float a = sA[t * 65 + k];
                s += a * u[k];
                d += a * v[k];
            }
            as_[node] = s;
            ad_[node] = d;
        }
    }
}

// ---------------- GAT pass 1: per-edge alpha + per-dst max ----------------
__global__ __launch_bounds__(256) void k_gat_alpha_max(
    const float* __restrict__ as_, const float* __restrict__ ad_,
    const int* __restrict__ offs, const int* __restrict__ ssrc,
    float* __restrict__ alpha, float* __restrict__ dmax, int n) {
    int warp = (blockIdx.x * blockDim.x + threadIdx.x) >> 5;
    int lane = threadIdx.x & 31;
    if (warp >= n) return;
    int start = offs[warp], end = offs[warp + 1];
    float adn = ad_[warp];
    float m = -INFINITY;
    for (int e = start + lane; e < end; e += 32) {
        float a = as_[ssrc[e]] + adn;
        a = a > 0.f ? a : NEG_SLOPE * a;
        alpha[e] = a;
        m = fmaxf(m, a);
    }
    #pragma unroll
    for (int o = 16; o; o >>= 1) m = fmaxf(m, __shfl_xor_sync(0xffffffffu, m, o));
    if (lane == 0) dmax[warp] = m;
}

// ---------------- GAT pass 2: softmax weights + weighted aggregation ----------------
__global__ __launch_bounds__(256) void k_gat_aggregate(
    const float* __restrict__ h,
    const float* __restrict__ alpha, const float* __restrict__ dmax,
    const int* __restrict__ offs, const int* __restrict__ ssrc,
    const float* __restrict__ bias,
    float* __restrict__ out, int n) {
    int warp = (blockIdx.x * blockDim.x + threadIdx.x) >> 5;
    int lane = threadIdx.x & 31;
    if (warp >= n) return;
    int start = offs[warp], end = offs[warp + 1];
    float m = dmax[warp];

    float acc0 = 0.f, acc1 = 0.f, den = 0.f;
    for (int eb = start; eb < end; eb += 32) {
        int e = eb + lane;
        float ex = 0.f; int s = 0;
        if (e < end) {
            s = ssrc[e];
            ex = __expf(alpha[e] - m);
        }
        den += ex;
        int cnt = min(32, end - eb);
        for (int j = 0; j < cnt; j++) {
            float w = __shfl_sync(0xffffffffu, ex, j);
            int sj  = __shfl_sync(0xffffffffu, s, j);
            const float* hp = h + (size_t)sj * H;
            acc0 += w * hp[lane];
            acc1 += w * hp[lane + 32];
        }
    }
    #pragma unroll
    for (int o = 16; o; o >>= 1) den += __shfl_xor_sync(0xffffffffu, den, o);
    float inv = 1.f / den;
    out[(size_t)warp * H + lane]      = acc0 * inv + bias[lane];
    out[(size_t)warp * H + lane + 32] = acc1 * inv + bias[lane + 32];
}

// ---------------- virtual-node segment sum (atomic into 256x64) ----------------
__global__ void k_vn_segsum(const float* __restrict__ out, const int* __restrict__ hb,
                            float* vn_tmp, int n) {
    int warp = (blockIdx.x * blockDim.x + threadIdx.x) >> 5;
    int lane = threadIdx.x & 31;
    if (warp >= n) return;
    int b = hb[warp];
    atomicAdd(&vn_tmp[b * H + lane],      out[(size_t)warp * H + lane]);
    atomicAdd(&vn_tmp[b * H + lane + 32], out[(size_t)warp * H + lane + 32]);
}

// ---------------- vn update: direct += seg + root; root += colsum(direct) ----------------
__global__ void k_vn_update(float* vn, const float* __restrict__ vn_tmp) {
    int t = threadIdx.x;  // 256
    for (int i = t; i < HNUM * H; i += 256) {
        vn[i] = vn[i] + vn_tmp[i] + vn[HNUM * H + (i & (H - 1))];
    }
    __syncthreads();
    if (t < H) {
        float s = 0.f;
        for (int r = 0; r < HNUM; r++) s += vn[r * H + t];
        vn[HNUM * H + t] += s;
    }
}

// ---------------- fused 2-layer MLP with ReLUs on vn rows (in place) ----------------
__global__ __launch_bounds__(256) void k_mlp_fused(
    float* vn, const float* __restrict__ w1, const float* __restrict__ b1,
    const float* __restrict__ w2, const float* __restrict__ b2, int rows) {
    __shared__ __align__(16) float sW[H * H];
    __shared__ float sV[64 * 65];
    int t = threadIdx.x;
    for (int i = t; i < H * H; i += 256) sW[i] = w1[i];
    int r0 = blockIdx.x * 64;
    for (int i = t; i < 64 * H; i += 256) {
        int r = i >> 6, c = i & 63;
        sV[r * 65 + c] = (r0 + r < rows) ? vn[(r0 + r) * H + c] : 0.f;
    }
    __syncthreads();
    int ty = t >> 4, tx = t & 15;
    float acc[4][4] = {};
    #pragma unroll 8
    for (int k = 0; k < H; k++) {
        float a0 = sV[(ty * 4 + 0) * 65 + k];
        float a1 = sV[(ty * 4 + 1) * 65 + k];
        float a2 = sV[(ty * 4 + 2) * 65 + k];
        float a3 = sV[(ty * 4 + 3) * 65 + k];
        float4 w4 = *(const float4*)&sW[k * H + tx * 4];
        acc[0][0] += a0 * w4.x; acc[0][1] += a0 * w4.y; acc[0][2] += a0 * w4.z; acc[0][3] += a0 * w4.w;
        acc[1][0] += a1 * w4.x; acc[1][1] += a1 * w4.y; acc[1][2] += a1 * w4.z; acc[1][3] += a1 * w4.w;
        acc[2][0] += a2 * w4.x; acc[2][1] += a2 * w4.y; acc[2][2] += a2 * w4.z; acc[2][3] += a2 * w4.w;
        acc[3][0] += a3 * w4.x; acc[3][1] += a3 * w4.y; acc[3][2] += a3 * w4.z; acc[3][3] += a3 * w4.w;
    }
    __syncthreads();  // all reads of sV / sW(w1) done
    #pragma unroll
    for (int i = 0; i < 4; i++) {
        #pragma unroll
        for (int j = 0; j < 4; j++) {
            float vbl = acc[i][j] + b1[tx * 4 + j];
            sV[(ty * 4 + i) * 65 + tx * 4 + j] = vbl > 0.f ? vbl : 0.f;
        }
    }
    for (int i = t; i < H * H; i += 256) sW[i] = w2[i];
    __syncthreads();
    float acc2[4][4] = {};
    #pragma unroll 8
    for (int k = 0; k < H; k++) {
        float a0 = sV[(ty * 4 + 0) * 65 + k];
        float a1 = sV[(ty * 4 + 1) * 65 + k];
        float a2 = sV[(ty * 4 + 2) * 65 + k];
        float a3 = sV[(ty * 4 + 3) * 65 + k];
        float4 w4 = *(const float4*)&sW[k * H + tx * 4];
        acc2[0][0] += a0 * w4.x; acc2[0][1] += a0 * w4.y; acc2[0][2] += a0 * w4.z; acc2[0][3] += a0 * w4.w;
        acc2[1][0] += a1 * w4.x; acc2[1][1] += a1 * w4.y; acc2[1][2] += a1 * w4.z; acc2[1][3] += a1 * w4.w;
        acc2[2][0] += a2 * w4.x; acc2[2][1] += a2 * w4.y; acc2[2][2] += a2 * w4.z; acc2[2][3] += a2 * w4.w;
        acc2[3][0] += a3 * w4.x; acc2[3][1] += a3 * w4.y; acc2[3][2] += a3 * w4.z; acc2[3][3] += a3 * w4.w;
    }
    #pragma unroll
    for (int i = 0; i < 4; i++) {
        int r = r0 + ty * 4 + i;
        if (r < rows) {
            #pragma unroll
            for (int j = 0; j < 4; j++) {
                float vbl = acc2[i][j] + b2[tx * 4 + j];
                vn[r * H + tx * 4 + j] = vbl > 0.f ? vbl : 0.f;
            }
        }
    }
}

// ---------------- host launch ----------------
extern "C" void kernel_launch(void* const* d_in, const int* in_sizes, int n_in,
                              void* d_out, int out_size) {
    const float* x  = (const float*)d_in[0];
    const int*   ei = (const int*)d_in[1];
    const int*   hb = (const int*)d_in[2];
    int base = (n_in >= 18) ? 5 : 4;
    const float* w_in     = (const float*)d_in[base + 0];
    const float* a_src_in = (const float*)d_in[base + 1];
    const float* a_dst_in = (const float*)d_in[base + 2];
    const float* b_in     = (const float*)d_in[base + 3];
    const float* w_l      = (const float*)d_in[base + 4];
    const float* a_src_l  = (const float*)d_in[base + 5];
    const float* a_dst_l  = (const float*)d_in[base + 6];
    const float* b_l      = (const float*)d_in[base + 7];
    const float* mw1      = (const float*)d_in[base + 8];
    const float* mb1      = (const float*)d_in[base + 9];
    const float* mw2      = (const float*)d_in[base + 10];
    const float* mb2      = (const float*)d_in[base + 11];
    const float* vne      = (const float*)d_in[base + 12];

    int N = in_sizes[0] / 3;
    int E = in_sizes[1] / 2;

    float *ph, *pout, *pas, *pad, *palpha, *pvn, *pvntmp, *pwain, *puv;
    int *pdeg, *poffs, *pcur, *pssrc, *pbsum, *pbsumex;
    cudaGetSymbolAddress((void**)&ph, g_h);
    cudaGetSymbolAddress((void**)&pout, g_out);
    cudaGetSymbolAddress((void**)&pas, g_as);
    cudaGetSymbolAddress((void**)&pad, g_ad);
    cudaGetSymbolAddress((void**)&palpha, g_alpha);
    cudaGetSymbolAddress((void**)&pdeg, g_deg);
    cudaGetSymbolAddress((void**)&poffs, g_offs);
    cudaGetSymbolAddress((void**)&pcur, g_cur);
    cudaGetSymbolAddress((void**)&pssrc, g_ssrc);
    cudaGetSymbolAddress((void**)&pbsum, g_bsum);
    cudaGetSymbolAddress((void**)&pbsumex, g_bsum_ex);
    cudaGetSymbolAddress((void**)&pvn, g_vn);
    cudaGetSymbolAddress((void**)&pvntmp, g_vntmp);
    cudaGetSymbolAddress((void**)&pwain, g_wain);
    cudaGetSymbolAddress((void**)&puv, g_uv);

    int nwarp_blocks = (N + 7) / 8;          // 8 warps per 256-thread block
    int gemm_blocks  = (N + 63) / 64;
    int nb = (N + SCAN_TILE - 1) / SCAN_TILE;
    // dmax scratch aliases g_cur? no — reuse g_bsum? too small. Use g_deg as dmax
    // after CSR build (deg no longer needed once offs built). Reinterpret as float*.
    float* pdmax = (float*)pdeg;

    // prep + CSR build
    k_prep<<<1, 256>>>(w_in, a_src_in, a_dst_in, w_l, a_src_l, a_dst_l, pwain, puv);
    k_initdeg<<<(N + 255) / 256, 256>>>(pdeg, N);
    k_hist<<<(E + 255) / 256, 256>>>(ei, pdeg, E);
    k_scan_blk<<<nb, SCAN_TILE>>>(pdeg, poffs, pbsum, N);
    k_scan_top<<<1, 128>>>(pbsum, pbsumex, nb);
    k_scan_add<<<nb, SCAN_TILE>>>(poffs, pcur, pbsumex, N, nb);
    k_scatter<<<(E + N + 255) / 256, 256>>>(ei, pcur, pssrc, E, N);
    k_vninit<<<((HNUM + 1) * H + 255) / 256, 256>>>(pvn, vne);

    // input GAT layer
    k_input_transform<<<nwarp_blocks, 256>>>(x, w_in, pwain, ph, pas, pad, N);
    k_gat_alpha_max<<<nwarp_blocks, 256>>>(pas, pad, poffs, pssrc, palpha, pdmax, N);
    k_gat_aggregate<<<nwarp_blocks, 256>>>(ph, palpha, pdmax, poffs, pssrc, b_in, pout, N);

    // l = 0
    k_gemm64<<<gemm_blocks, 256>>>(pout, w_l, puv, puv + H, pvn, hb, ph, pas, pad, N);
    k_gat_alpha_max<<<nwarp_blocks, 256>>>(pas, pad, poffs, pssrc, palpha, pdmax, N);
    k_gat_aggregate<<<nwarp_blocks, 256>>>(ph, palpha, pdmax, poffs, pssrc, b_l, pout, N);
    k_zero<<<(HNUM * H + 255) / 256, 256>>>(pvntmp, HNUM * H);
    k_vn_segsum<<<nwarp_blocks, 256>>>(pout, hb, pvntmp, N);
    k_vn_update<<<1, 256>>>(pvn, pvntmp);
    k_mlp_fused<<<(HNUM + 1 + 63) / 64, 256>>>(pvn, mw1, mb1, mw2, mb2, HNUM + 1);
    k_mlp_fused<<<(HNUM + 1 + 63) / 64, 256>>>(pvn, mw1 + H * H, mb1 + H,
                                               mw2 + H * H, mb2 + H, HNUM + 1);

    // l = 1 (vn updates after the last GAT never affect the output -> skipped)
    k_gemm64<<<gemm_blocks, 256>>>(pout, w_l + H * H, puv + 2 * H, puv + 3 * H,
                                   pvn, hb, ph, pas, pad, N);
    k_gat_alpha_max<<<nwarp_blocks, 256>>>(pas, pad, poffs, pssrc, palpha, pdmax, N);
    k_gat_aggregate<<<nwarp_blocks, 256>>>(ph, palpha, pdmax, poffs, pssrc, b_l + H,
                                           (float*)d_out, N);
}

// round 3
// speedup vs baseline: 1.4236x; 1.2952x over previous
#include <cuda_runtime.h>
#include <math.h>

#define H 64
#define HNUM 256
#define NMAX 100000
#define EMAX 1200000
#define NEG_SLOPE 0.2f
#define CAP 128

// ---------------- scratch (static device globals; zero-initialized at load) ----------------
__device__ float g_h[(size_t)NMAX * H];
__device__ float g_out[(size_t)NMAX * H];
__device__ float g_as[NMAX];
__device__ float g_ad[NMAX];
__device__ int   g_deg[NMAX];          // consume-and-reset: zero on entry to each call
__device__ int   g_st[NMAX];
__device__ int   g_en[NMAX];
__device__ int   g_cur[NMAX];
__device__ int   g_total;              // reset by k_hist each call
__device__ int   g_ssrc[EMAX + NMAX];
__device__ float g_vn[(HNUM + 1) * H]; // rows 0..255 vn_direct, row 256 vn_root
__device__ float g_vntmp[HNUM * H];
__device__ float g_wain[6];
__device__ float g_uv[4 * H];

// ---------------- input transform: h = x@W_in, as/ad = x@wa ----------------
__global__ void k_input_transform(const float* __restrict__ x,
                                  const float* __restrict__ w_in,
                                  const float* __restrict__ a_src_in,
                                  const float* __restrict__ a_dst_in,
                                  float* __restrict__ h,
                                  float* __restrict__ as_, float* __restrict__ ad_,
                                  int n) {
    __shared__ float sW[3 * H];
    __shared__ float swa[6];
    int t = threadIdx.x;
    if (t < 3 * H) sW[t] = w_in[t];
    if (t < 6) {
        // wa[i] (src) = sum_k w_in[i*H+k] * a_src[k]; wa[3+i] (dst) likewise
        int i = t % 3;
        const float* av = (t >= 3) ? a_dst_in : a_src_in;
        float s2 = 0.f;
        #pragma unroll 8
        for (int k = 0; k < H; k++) s2 += w_in[i * H + k] * av[k];
        swa[t] = s2;
    }
    __syncthreads();
    int warp = (blockIdx.x * blockDim.x + t) >> 5;
    int lane = t & 31;
    if (warp >= n) return;
    float x0 = x[warp * 3 + 0], x1 = x[warp * 3 + 1], x2 = x[warp * 3 + 2];
    float ha = x0 * sW[lane]      + x1 * sW[H + lane]      + x2 * sW[2 * H + lane];
    float hb = x0 * sW[32 + lane] + x1 * sW[H + 32 + lane] + x2 * sW[2 * H + 32 + lane];
    h[(size_t)warp * H + lane]      = ha;
    h[(size_t)warp * H + lane + 32] = hb;
    if (lane == 0) {
        as_[warp] = x0 * swa[0] + x1 * swa[1] + x2 * swa[2];
        ad_[warp] = x0 * swa[3] + x1 * swa[4] + x2 * swa[5];
    }
}

// ---------------- CSR build: hist -> alloc -> scatter (no global scan) ----------------
__global__ void k_hist(const int* __restrict__ ei, int* deg, int* total, int E) {
    int i = blockIdx.x * blockDim.x + threadIdx.x;
    if (i == 0) *total = 0;
    if (i < E) atomicAdd(&deg[ei[E + i]], 1);
}

// per-node range allocation: block-local scan + one atomicAdd per block.
// Ranges are unique/disjoint but not ordered by node id — aggregation doesn't care.
__global__ __launch_bounds__(256) void k_alloc(int* __restrict__ deg,
                                               int* __restrict__ st,
                                               int* __restrict__ en,
                                               int* __restrict__ cur,
                                               int* total, int n) {
    __shared__ int sWarp[8];
    __shared__ int sBase;
    int t = threadIdx.x, lane = t & 31, w = t >> 5;
    int i = blockIdx.x * 256 + t;
    int d = 0;
    if (i < n) { d = deg[i] + 1; deg[i] = 0; }   // +1 self loop; reset for next call
    int x = d;
    #pragma unroll
    for (int o = 1; o < 32; o <<= 1) {
        int y = __shfl_up_sync(0xffffffffu, x, o);
        if (lane >= o) x += y;
    }
    if (lane == 31) sWarp[w] = x;
    __syncthreads();
    if (t == 0) {
        int s = 0;
        #pragma unroll
        for (int k = 0; k < 8; k++) { int v = sWarp[k]; sWarp[k] = s; s += v; }
        sBase = atomicAdd(total, s);
    }
    __syncthreads();
    int start = sBase + sWarp[w] + x - d;
    if (i < n) { st[i] = start; cur[i] = start; en[i] = start + d; }
}

__global__ void k_scatter(const int* __restrict__ ei, int* cur,
                          int* __restrict__ ssrc, int E, int n) {
    int i = blockIdx.x * blockDim.x + threadIdx.x;
    int total = E + n;
    if (i >= total) return;
    int s, d;
    if (i < E) { s = ei[i]; d = ei[E + i]; }
    else       { s = i - E; d = s; }
    int pos = atomicAdd(&cur[d], 1);
    ssrc[pos] = s;
}

// ---------------- setup: prep folded attention vecs + vn init + vntmp zero ----------------
__global__ void k_setup(const float* __restrict__ w_l,
                        const float* __restrict__ a_src_l,
                        const float* __restrict__ a_dst_l,
                        float* __restrict__ uv,
                        float* __restrict__ vn, float* __restrict__ vntmp,
                        const float* __restrict__ emb) {
    int b = blockIdx.x, t = threadIdx.x;
    if (b == 0) {
        // uv[(l*2+isdst)*H + j] = sum_k w_l[l][j][k] * a[l][k]
        int l = t >> 7;
        int isdst = (t >> 6) & 1;
        int j = t & 63;
        const float* a = isdst ? (a_dst_l + l * H) : (a_src_l + l * H);
        const float* W = w_l + l * H * H;
        float s = 0.f;
        #pragma unroll 8
        for (int k = 0; k < H; k++) s += W[j * H + k] * a[k];
        uv[(l * 2 + isdst) * H + j] = s;
    } else if (b <= 65) {
        int i = (b - 1) * 256 + t;
        if (i < (HNUM + 1) * H) vn[i] = emb[i & (H - 1)];
    } else {
        int i = (b - 66) * 256 + t;
        if (i < HNUM * H) vntmp[i] = 0.f;
    }
}

// ---------------- hidden-layer GEMM: Hout = (A + vn[hb]) @ W, plus as/ad ----------------
__global__ __launch_bounds__(256) void k_gemm64(
    const float* __restrict__ A, const float* __restrict__ W,
    const float* __restrict__ u, const float* __restrict__ v,
    const float* __restrict__ vn, const int* __restrict__ hb,
    float* __restrict__ Hout, float* __restrict__ as_, float* __restrict__ ad_,
    int n) {
    __shared__ __align__(16) float sW[H * H];
    __shared__ float sA[64 * 65];
    int t = threadIdx.x;
    for (int i = t; i < H * H; i += 256) sW[i] = W[i];
    int block_row = blockIdx.x * 64;
    for (int i = t; i < 64 * H; i += 256) {
        int r = i >> 6, c = i & 63;
        int node = block_row + r;
        float val = 0.f;
        if (node < n) val = A[(size_t)node * H + c] + vn[hb[node] * H + c];
        sA[r * 65 + c] = val;
    }
    __syncthreads();
    int ty = t >> 4, tx = t & 15;
    float acc[4][4] = {};
    #pragma unroll 8
    for (int k = 0; k < H; k++) {
        float a0 = sA[(ty * 4 + 0) * 65 + k];
        float a1 = sA[(ty * 4 + 1) * 65 + k];
        float a2 = sA[(ty * 4 + 2) * 65 + k];
        float a3 = sA[(ty * 4 + 3) * 65 + k];
        float4 w4 = *(const float4*)&sW[k * H + tx * 4];
        acc[0][0] += a0 * w4.x; acc[0][1] += a0 * w4.y; acc[0][2] += a0 * w4.z; acc[0][3] += a0 * w4.w;
        acc[1][0] += a1 * w4.x; acc[1][1] += a1 * w4.y; acc[1][2] += a1 * w4.z; acc[1][3] += a1 * w4.w;
        acc[2][0] += a2 * w4.x; acc[2][1] += a2 * w4.y; acc[2][2] += a2 * w4.z; acc[2][3] += a2 * w4.w;
        acc[3][0] += a3 * w4.x; acc[3][1] += a3 * w4.y; acc[3][2] += a3 * w4.z; acc[3][3] += a3 * w4.w;
    }
    #pragma unroll
    for (int i = 0; i < 4; i++) {
        int node = block_row + ty * 4 + i;
        if (node < n) {
            float4 o4 = make_float4(acc[i][0], acc[i][1], acc[i][2], acc[i][3]);
            *(float4*)&Hout[(size_t)node * H + tx * 4] = o4;
        }
    }
    if (t < 64) {
        int node = block_row + t;
        if (node < n) {
            float s = 0.f, d = 0.f;
            #pragma unroll 8
            for (int k = 0; k < H; k++) {
                float a = sA[t * 65 + k];
                s += a * u[k];
                d += a * v[k];
            }
            as_[node] = s;
            ad_[node] = d;
        }
    }
}

// ---------------- fused GAT: alpha + max + softmax + aggregation (+ optional segsum) ----
__global__ __launch_bounds__(256) void k_gat(
    const float2* __restrict__ h2,
    const float* __restrict__ as_, const float* __restrict__ ad_,
    const int* __restrict__ st, const int* __restrict__ en,
    const int* __restrict__ ssrc,
    const float* __restrict__ bias,
    float* __restrict__ out,
    float* __restrict__ vntmp, const int* __restrict__ hb, int n) {
    __shared__ int   s_src[8][CAP];
    __shared__ float s_w[8][CAP];
    int t = threadIdx.x, lane = t & 31, w = t >> 5;
    int node = blockIdx.x * 8 + w;
    if (node >= n) return;
    int start = st[node], end = en[node];
    int deg = end - start;
    float adn = ad_[node];
    float2 acc = make_float2(0.f, 0.f);
    float den = 0.f;

    if (deg <= CAP) {
        float m = -INFINITY;
        for (int i = lane; i < deg; i += 32) {
            int s = ssrc[start + i];
            float a = as_[s] + adn;
            a = a > 0.f ? a : NEG_SLOPE * a;
            s_src[w][i] = s;
            s_w[w][i] = a;
            m = fmaxf(m, a);
        }
        #pragma unroll
        for (int o = 16; o; o >>= 1) m = fmaxf(m, __shfl_xor_sync(0xffffffffu, m, o));
        for (int i = lane; i < deg; i += 32) {
            float ex = __expf(s_w[w][i] - m);
            s_w[w][i] = ex;
            den += ex;
        }
        #pragma unroll
        for (int o = 16; o; o >>= 1) den += __shfl_xor_sync(0xffffffffu, den, o);
        __syncwarp();
        for (int j = 0; j < deg; j++) {
            float wj = s_w[w][j];
            float2 v = h2[(size_t)s_src[w][j] * 32 + lane];
            acc.x += wj * v.x;
            acc.y += wj * v.y;
        }
    } else {
        // rare fallback: two-pass recompute from global
        float m = -INFINITY;
        for (int e = start + lane; e < end; e += 32) {
            float a = as_[ssrc[e]] + adn;
            a = a > 0.f ? a : NEG_SLOPE * a;
            m = fmaxf(m, a);
        }
        #pragma unroll
        for (int o = 16; o; o >>= 1) m = fmaxf(m, __shfl_xor_sync(0xffffffffu, m, o));
        for (int eb = start; eb < end; eb += 32) {
            int e = eb + lane;
            float ex = 0.f; int s = 0;
            if (e < end) {
                s = ssrc[e];
                float a = as_[s] + adn;
                a = a > 0.f ? a : NEG_SLOPE * a;
                ex = __expf(a - m);
            }
            den += ex;
            int cnt = min(32, end - eb);
            for (int j = 0; j < cnt; j++) {
                float wj = __shfl_sync(0xffffffffu, ex, j);
                int sj   = __shfl_sync(0xffffffffu, s, j);
                float2 v = h2[(size_t)sj * 32 + lane];
                acc.x += wj * v.x;
                acc.y += wj * v.y;
            }
        }
        #pragma unroll
        for (int o = 16; o; o >>= 1) den += __shfl_xor_sync(0xffffffffu, den, o);
    }

    float inv = 1.f / den;
    float2 b = ((const float2*)bias)[lane];
    float2 o2 = make_float2(acc.x * inv + b.x, acc.y * inv + b.y);
    ((float2*)out)[(size_t)node * 32 + lane] = o2;
    if (vntmp) {
        int blk = hb[node];
        atomicAdd(&vntmp[blk * H + lane * 2],     o2.x);
        atomicAdd(&vntmp[blk * H + lane * 2 + 1], o2.y);
    }
}

// ---------------- vn update: direct += seg + root; root += colsum(direct) ----------------
__global__ __launch_bounds__(1024) void k_vn_update(float* vn, const float* __restrict__ vn_tmp) {
    __shared__ float red[16 * 64];
    int t = threadIdx.x;  // 1024
    for (int i = t; i < HNUM * H; i += 1024) {
        vn[i] = vn[i] + vn_tmp[i] + vn[HNUM * H + (i & (H - 1))];
    }
    __syncthreads();
    int col = t & 63, g = t >> 6;   // g in 0..15
    float s = 0.f;
    for (int r = g * 16; r < g * 16 + 16; r++) s += vn[r * H + col];
    red[g * 64 + col] = s;
    __syncthreads();
    if (t < 64) {
        float tot = 0.f;
        #pragma unroll
        for (int gg = 0; gg < 16; gg++) tot += red[gg * 64 + t];
        vn[HNUM * H + t] += tot;
    }
}

// ---------------- both vn MLPs in one kernel; rows stay in smem ----------------
__global__ __launch_bounds__(256) void k_mlp2(
    float* vn, const float* __restrict__ mw1, const float* __restrict__ mb1,
    const float* __restrict__ mw2, const float* __restrict__ mb2, int rows) {
    __shared__ __align__(16) float sW[H * H];
    __shared__ float sV[64 * 65];
    int t = threadIdx.x;
    int r0 = blockIdx.x * 64;
    for (int i = t; i < 64 * H; i += 256) {
        int r = i >> 6, c = i & 63;
        sV[r * 65 + c] = (r0 + r < rows) ? vn[(r0 + r) * H + c] : 0.f;
    }
    int ty = t >> 4, tx = t & 15;
    for (int m = 0; m < 2; m++) {
        const float* w1 = mw1 + m * H * H;
        const float* b1 = mb1 + m * H;
        const float* w2 = mw2 + m * H * H;
        const float* b2 = mb2 + m * H;
        for (int i = t; i < H * H; i += 256) sW[i] = w1[i];
        __syncthreads();
        float acc[4][4] = {};
        #pragma unroll 8
        for (int k = 0; k < H; k++) {
            float a0 = sV[(ty * 4 + 0) * 65 + k];
            float a1 = sV[(ty * 4 + 1) * 65 + k];
            float a2 = sV[(ty * 4 + 2) * 65 + k];
            float a3 = sV[(ty * 4 + 3) * 65 + k];
            float4 w4 = *(const float4*)&sW[k * H + tx * 4];
            acc[0][0] += a0 * w4.x; acc[0][1] += a0 * w4.y; acc[0][2] += a0 * w4.z; acc[0][3] += a0 * w4.w;
            acc[1][0] += a1 * w4.x; acc[1][1] += a1 * w4.y; acc[1][2] += a1 * w4.z; acc[1][3] += a1 * w4.w;
            acc[2][0] += a2 * w4.x; acc[2][1] += a2 * w4.y; acc[2][2] += a2 * w4.z; acc[2][3] += a2 * w4.w;
            acc[3][0] += a3 * w4.x; acc[3][1] += a3 * w4.y; acc[3][2] += a3 * w4.z; acc[3][3] += a3 * w4.w;
        }
        __syncthreads();
        #pragma unroll
        for (int i = 0; i < 4; i++)
            #pragma unroll
            for (int j = 0; j < 4; j++) {
                float vbl = acc[i][j] + b1[tx * 4 + j];
                sV[(ty * 4 + i) * 65 + tx * 4 + j] = vbl > 0.f ? vbl : 0.f;
            }
        for (int i = t; i < H * H; i += 256) sW[i] = w2[i];
        __syncthreads();
        float acc2[4][4] = {};
        #pragma unroll 8
        for (int k = 0; k < H; k++) {
            float a0 = sV[(ty * 4 + 0) * 65 + k];
            float a1 = sV[(ty * 4 + 1) * 65 + k];
            float a2 = sV[(ty * 4 + 2) * 65 + k];
            float a3 = sV[(ty * 4 + 3) * 65 + k];
            float4 w4 = *(const float4*)&sW[k * H + tx * 4];
            acc2[0][0] += a0 * w4.x; acc2[0][1] += a0 * w4.y; acc2[0][2] += a0 * w4.z; acc2[0][3] += a0 * w4.w;
            acc2[1][0] += a1 * w4.x; acc2[1][1] += a1 * w4.y; acc2[1][2] += a1 * w4.z; acc2[1][3] += a1 * w4.w;
            acc2[2][0] += a2 * w4.x; acc2[2][1] += a2 * w4.y; acc2[2][2] += a2 * w4.z; acc2[2][3] += a2 * w4.w;
            acc2[3][0] += a3 * w4.x; acc2[3][1] += a3 * w4.y; acc2[3][2] += a3 * w4.z; acc2[3][3] += a3 * w4.w;
        }
        __syncthreads();
        #pragma unroll
        for (int i = 0; i < 4; i++)
            #pragma unroll
            for (int j = 0; j < 4; j++) {
                float vbl = acc2[i][j] + b2[tx * 4 + j];
                sV[(ty * 4 + i) * 65 + tx * 4 + j] = vbl > 0.f ? vbl : 0.f;
            }
        __syncthreads();
    }
    for (int i = t; i < 64 * H; i += 256) {
        int r = i >> 6, c = i & 63;
        if (r0 + r < rows) vn[(r0 + r) * H + c] = sV[r * 65 + c];
    }
}

// ---------------- host launch ----------------
extern "C" void kernel_launch(void* const* d_in, const int* in_sizes, int n_in,
                              void* d_out, int out_size) {
    const float* x  = (const float*)d_in[0];
    const int*   ei = (const int*)d_in[1];
    const int*   hb = (const int*)d_in[2];
    int base = (n_in >= 18) ? 5 : 4;
    const float* w_in     = (const float*)d_in[base + 0];
    const float* a_src_in = (const float*)d_in[base + 1];
    const float* a_dst_in = (const float*)d_in[base + 2];
    const float* b_in     = (const float*)d_in[base + 3];
    const float* w_l      = (const float*)d_in[base + 4];
    const float* a_src_l  = (const float*)d_in[base + 5];
    const float* a_dst_l  = (const float*)d_in[base + 6];
    const float* b_l      = (const float*)d_in[base + 7];
    const float* mw1      = (const float*)d_in[base + 8];
    const float* mb1      = (const float*)d_in[base + 9];
    const float* mw2      = (const float*)d_in[base + 10];
    const float* mb2      = (const float*)d_in[base + 11];
    const float* vne      = (const float*)d_in[base + 12];

    int N = in_sizes[0] / 3;
    int E = in_sizes[1] / 2;

    float *ph, *pout, *pas, *pad, *pvn, *pvntmp, *puv;
    int *pdeg, *pst, *pen, *pcur, *pssrc, *ptotal;
    cudaGetSymbolAddress((void**)&ph, g_h);
    cudaGetSymbolAddress((void**)&pout, g_out);
    cudaGetSymbolAddress((void**)&pas, g_as);
    cudaGetSymbolAddress((void**)&pad, g_ad);
    cudaGetSymbolAddress((void**)&pdeg, g_deg);
    cudaGetSymbolAddress((void**)&pst, g_st);
    cudaGetSymbolAddress((void**)&pen, g_en);
    cudaGetSymbolAddress((void**)&pcur, g_cur);
    cudaGetSymbolAddress((void**)&pssrc, g_ssrc);
    cudaGetSymbolAddress((void**)&ptotal, g_total);
    cudaGetSymbolAddress((void**)&pvn, g_vn);
    cudaGetSymbolAddress((void**)&pvntmp, g_vntmp);
    cudaGetSymbolAddress((void**)&puv, g_uv);

    int nwarp_blocks = (N + 7) / 8;
    int gemm_blocks  = (N + 63) / 64;

    // 0: input transform (independent of CSR)
    k_input_transform<<<nwarp_blocks, 256>>>(x, w_in, a_src_in, a_dst_in, ph, pas, pad, N);
    // 1-3: CSR build (scan-free)
    k_hist<<<(E + 255) / 256, 256>>>(ei, pdeg, ptotal, E);
    k_alloc<<<(N + 255) / 256, 256>>>(pdeg, pst, pen, pcur, ptotal, N);
    k_scatter<<<(E + N + 255) / 256, 256>>>(ei, pcur, pssrc, E, N);
    // 4: setup (folded attention vecs + vn init + vntmp zero)
    k_setup<<<130, 256>>>(w_l, a_src_l, a_dst_l, puv, pvn, pvntmp, vne);

    // 5: input GAT layer
    k_gat<<<nwarp_blocks, 256>>>((const float2*)ph, pas, pad, pst, pen, pssrc,
                                 b_in, pout, nullptr, nullptr, N);
    // 6-9: l = 0
    k_gemm64<<<gemm_blocks, 256>>>(pout, w_l, puv, puv + H, pvn, hb, ph, pas, pad, N);
    k_gat<<<nwarp_blocks, 256>>>((const float2*)ph, pas, pad, pst, pen, pssrc,
                                 b_l, pout, pvntmp, hb, N);
    k_vn_update<<<1, 1024>>>(pvn, pvntmp);
    k_mlp2<<<(HNUM + 1 + 63) / 64, 256>>>(pvn, mw1, mb1, mw2, mb2, HNUM + 1);

    // 10-11: l = 1 (trailing vn updates are dead code w.r.t. output)
    k_gemm64<<<gemm_blocks, 256>>>(pout, w_l + H * H, puv + 2 * H, puv + 3 * H,
                                   pvn, hb, ph, pas, pad, N);
    k_gat<<<nwarp_blocks, 256>>>((const float2*)ph, pas, pad, pst, pen, pssrc,
                                 b_l + H, (float*)d_out, nullptr, nullptr, N);
}

// round 4
// speedup vs baseline: 1.5870x; 1.1148x over previous
#include <cuda_runtime.h>
#include <math.h>

#define H 64
#define HNUM 256
#define NMAX 100000
#define EMAX 1200000
#define NEG_SLOPE 0.2f
#define CAP 128

// ---------------- scratch (static device globals) ----------------
__device__ float g_h[(size_t)NMAX * H];
__device__ float g_out[(size_t)NMAX * H];
__device__ float g_as[NMAX];
__device__ float g_ad[NMAX];
__device__ int   g_deg[NMAX];          // consume-and-reset each call
__device__ int   g_st[NMAX];
__device__ int   g_en[NMAX];
__device__ int   g_cur[NMAX];
__device__ int   g_total;
__device__ int   g_ssrc[EMAX + NMAX];
__device__ float g_vn[(HNUM + 1) * H]; // rows 0..255 vn_direct, row 256 vn_root
__device__ float g_vntmp[HNUM * H];
__device__ float g_uv[4 * H];

// ---------------- CSR build: hist -> alloc -> scatter (no global scan) ----------------
__global__ void k_hist(const int* __restrict__ ei, int* deg, int* total, int E) {
    int i = blockIdx.x * blockDim.x + threadIdx.x;
    if (i == 0) *total = 0;
    if (i < E) atomicAdd(&deg[ei[E + i]], 1);
}

__global__ __launch_bounds__(256) void k_alloc(int* __restrict__ deg,
                                               int* __restrict__ st,
                                               int* __restrict__ en,
                                               int* __restrict__ cur,
                                               int* total, int n) {
    __shared__ int sWarp[8];
    __shared__ int sBase;
    int t = threadIdx.x, lane = t & 31, w = t >> 5;
    int i = blockIdx.x * 256 + t;
    int d = 0;
    if (i < n) { d = deg[i] + 1; deg[i] = 0; }   // +1 self loop; reset for next call
    int x = d;
    #pragma unroll
    for (int o = 1; o < 32; o <<= 1) {
        int y = __shfl_up_sync(0xffffffffu, x, o);
        if (lane >= o) x += y;
    }
    if (lane == 31) sWarp[w] = x;
    __syncthreads();
    if (t == 0) {
        int s = 0;
        #pragma unroll
        for (int k = 0; k < 8; k++) { int v = sWarp[k]; sWarp[k] = s; s += v; }
        sBase = atomicAdd(total, s);
    }
    __syncthreads();
    int start = sBase + sWarp[w] + x - d;
    if (i < n) { st[i] = start; cur[i] = start; en[i] = start + d; }
}

__global__ void k_scatter(const int* __restrict__ ei, int* cur,
                          int* __restrict__ ssrc, int E, int n) {
    int i = blockIdx.x * blockDim.x + threadIdx.x;
    int total = E + n;
    if (i >= total) return;
    int s, d;
    if (i < E) { s = ei[i]; d = ei[E + i]; }
    else       { s = i - E; d = s; }
    int pos = atomicAdd(&cur[d], 1);
    ssrc[pos] = s;
}

// ---------------- setup: uv folding + vn init + vntmp zero + per-node as/ad ----------------
__global__ void k_setup(const float* __restrict__ x,
                        const float* __restrict__ w_in,
                        const float* __restrict__ a_src_in,
                        const float* __restrict__ a_dst_in,
                        const float* __restrict__ w_l,
                        const float* __restrict__ a_src_l,
                        const float* __restrict__ a_dst_l,
                        float* __restrict__ uv,
                        float* __restrict__ vn, float* __restrict__ vntmp,
                        const float* __restrict__ emb,
                        float* __restrict__ as_, float* __restrict__ ad_, int n) {
    int b = blockIdx.x, t = threadIdx.x;
    if (b == 0) {
        // uv[(l*2+isdst)*H + j] = sum_k w_l[l][j][k] * a[l][k]
        int l = t >> 7;
        int isdst = (t >> 6) & 1;
        int j = t & 63;
        const float* a = isdst ? (a_dst_l + l * H) : (a_src_l + l * H);
        const float* W = w_l + l * H * H;
        float s = 0.f;
        #pragma unroll 8
        for (int k = 0; k < H; k++) s += W[j * H + k] * a[k];
        uv[(l * 2 + isdst) * H + j] = s;
    } else if (b <= 65) {
        int i = (b - 1) * 256 + t;
        if (i < (HNUM + 1) * H) vn[i] = emb[i & (H - 1)];
    } else if (b <= 129) {
        int i = (b - 66) * 256 + t;
        if (i < HNUM * H) vntmp[i] = 0.f;
    } else {
        // per-node input-layer attention scalars: as = x . (W_in a_src), ad likewise
        __shared__ float swa[6];
        if (t < 6) {
            int i = t % 3;
            const float* av = (t >= 3) ? a_dst_in : a_src_in;
            float s2 = 0.f;
            #pragma unroll 8
            for (int k = 0; k < H; k++) s2 += w_in[i * H + k] * av[k];
            swa[t] = s2;
        }
        __syncthreads();
        int i = (b - 130) * 256 + t;
        if (i < n) {
            float x0 = x[3 * i], x1 = x[3 * i + 1], x2 = x[3 * i + 2];
            as_[i] = x0 * swa[0] + x1 * swa[1] + x2 * swa[2];
            ad_[i] = x0 * swa[3] + x1 * swa[4] + x2 * swa[5];
        }
    }
}

// ---------------- layer-1 GAT: aggregate raw x (3 floats/edge), W_in applied after ----
__global__ __launch_bounds__(256) void k_gat_in(
    const float* __restrict__ x,
    const float* __restrict__ as_, const float* __restrict__ ad_,
    const int* __restrict__ st, const int* __restrict__ en,
    const int* __restrict__ ssrc,
    const float* __restrict__ w_in, const float* __restrict__ b_in,
    float* __restrict__ out, int n) {
    __shared__ int   s_src[8][CAP];
    __shared__ float s_w[8][CAP];
    __shared__ float sW[3 * H];
    int t = threadIdx.x, lane = t & 31, w = t >> 5;
    if (t < 3 * H) sW[t] = w_in[t];
    __syncthreads();
    int node = blockIdx.x * 8 + w;
    if (node >= n) return;
    int start = st[node], end = en[node];
    int deg = end - start;
    float adn = ad_[node];
    float a0 = 0.f, a1 = 0.f, a2 = 0.f, den = 0.f;

    if (deg <= CAP) {
        float m = -INFINITY;
        for (int i = lane; i < deg; i += 32) {
            int s = ssrc[start + i];
            float a = as_[s] + adn;
            a = a > 0.f ? a : NEG_SLOPE * a;
            s_src[w][i] = s;
            s_w[w][i] = a;
            m = fmaxf(m, a);
        }
        #pragma unroll
        for (int o = 16; o; o >>= 1) m = fmaxf(m, __shfl_xor_sync(0xffffffffu, m, o));
        __syncwarp();
        for (int i = lane; i < deg; i += 32) {
            float ex = __expf(s_w[w][i] - m);
            den += ex;
            const float* xp = x + 3 * (size_t)s_src[w][i];
            a0 += ex * xp[0];
            a1 += ex * xp[1];
            a2 += ex * xp[2];
        }
    } else {
        float m = -INFINITY;
        for (int e = start + lane; e < end; e += 32) {
            float a = as_[ssrc[e]] + adn;
            a = a > 0.f ? a : NEG_SLOPE * a;
            m = fmaxf(m, a);
        }
        #pragma unroll
        for (int o = 16; o; o >>= 1) m = fmaxf(m, __shfl_xor_sync(0xffffffffu, m, o));
        for (int e = start + lane; e < end; e += 32) {
            int s = ssrc[e];
            float a = as_[s] + adn;
            a = a > 0.f ? a : NEG_SLOPE * a;
            float ex = __expf(a - m);
            den += ex;
            const float* xp = x + 3 * (size_t)s;
            a0 += ex * xp[0];
            a1 += ex * xp[1];
            a2 += ex * xp[2];
        }
    }
    #pragma unroll
    for (int o = 16; o; o >>= 1) {
        a0  += __shfl_xor_sync(0xffffffffu, a0, o);
        a1  += __shfl_xor_sync(0xffffffffu, a1, o);
        a2  += __shfl_xor_sync(0xffffffffu, a2, o);
        den += __shfl_xor_sync(0xffffffffu, den, o);
    }
    float inv = 1.f / den;
    a0 *= inv; a1 *= inv; a2 *= inv;
    float c0 = a0 * sW[lane]      + a1 * sW[H + lane]      + a2 * sW[2 * H + lane]      + b_in[lane];
    float c1 = a0 * sW[32 + lane] + a1 * sW[H + 32 + lane] + a2 * sW[2 * H + 32 + lane] + b_in[lane + 32];
    out[(size_t)node * H + lane]      = c0;
    out[(size_t)node * H + lane + 32] = c1;
}

// ---------------- hidden-layer GEMM: Hout = (A + vn[hb]) @ W, plus as/ad ----------------
__global__ __launch_bounds__(256) void k_gemm64(
    const float* __restrict__ A, const float* __restrict__ W,
    const float* __restrict__ u, const float* __restrict__ v,
    const float* __restrict__ vn, const int* __restrict__ hb,
    float* __restrict__ Hout, float* __restrict__ as_, float* __restrict__ ad_,
    int n) {
    __shared__ __align__(16) float sW[H * H];
    __shared__ float sA[64 * 65];
    int t = threadIdx.x;
    for (int i = t; i < H * H; i += 256) sW[i] = W[i];
    int block_row = blockIdx.x * 64;
    for (int i = t; i < 64 * H; i += 256) {
        int r = i >> 6, c = i & 63;
        int node = block_row + r;
        float val = 0.f;
        if (node < n) val = A[(size_t)node * H + c] + vn[hb[node] * H + c];
        sA[r * 65 + c] = val;
    }
    __syncthreads();
    int ty = t >> 4, tx = t & 15;
    float acc[4][4] = {};
    #pragma unroll 8
    for (int k = 0; k < H; k++) {
        float a0 = sA[(ty * 4 + 0) * 65 + k];
        float a1 = sA[(ty * 4 + 1) * 65 + k];
        float a2 = sA[(ty * 4 + 2) * 65 + k];
        float a3 = sA[(ty * 4 + 3) * 65 + k];
        float4 w4 = *(const float4*)&sW[k * H + tx * 4];
        acc[0][0] += a0 * w4.x; acc[0][1] += a0 * w4.y; acc[0][2] += a0 * w4.z; acc[0][3] += a0 * w4.w;
        acc[1][0] += a1 * w4.x; acc[1][1] += a1 * w4.y; acc[1][2] += a1 * w4.z; acc[1][3] += a1 * w4.w;
        acc[2][0] += a2 * w4.x; acc[2][1] += a2 * w4.y; acc[2][2] += a2 * w4.z; acc[2][3] += a2 * w4.w;
        acc[3][0] += a3 * w4.x; acc[3][1] += a3 * w4.y; acc[3][2] += a3 * w4.z; acc[3][3] += a3 * w4.w;
    }
    #pragma unroll
    for (int i = 0; i < 4; i++) {
        int node = block_row + ty * 4 + i;
        if (node < n) {
            float4 o4 = make_float4(acc[i][0], acc[i][1], acc[i][2], acc[i][3]);
            *(float4*)&Hout[(size_t)node * H + tx * 4] = o4;
        }
    }
    if (t < 64) {
        int node = block_row + t;
        if (node < n) {
            float s = 0.f, d = 0.f;
            #pragma unroll 8
            for (int k = 0; k < H; k++) {
                float a = sA[t * 65 + k];
                s += a * u[k];
                d += a * v[k];
            }
            as_[node] = s;
            ad_[node] = d;
        }
    }
}

// ---------------- hidden GAT: alpha + softmax + h-gather aggregation (+ opt segsum) ----
__global__ __launch_bounds__(256) void k_gat(
    const float2* __restrict__ h2,
    const float* __restrict__ as_, const float* __restrict__ ad_,
    const int* __restrict__ st, const int* __restrict__ en,
    const int* __restrict__ ssrc,
    const float* __restrict__ bias,
    float* __restrict__ out,
    float* __restrict__ vntmp, const int* __restrict__ hb, int n) {
    __shared__ int   s_src[8][CAP];
    __shared__ float s_w[8][CAP];
    int t = threadIdx.x, lane = t & 31, w = t >> 5;
    int node = blockIdx.x * 8 + w;
    if (node >= n) return;
    int start = st[node], end = en[node];
    int deg = end - start;
    float adn = ad_[node];
    float2 acc = make_float2(0.f, 0.f);
    float den = 0.f;

    if (deg <= CAP) {
        float m = -INFINITY;
        for (int i = lane; i < deg; i += 32) {
            int s = ssrc[start + i];
            float a = as_[s] + adn;
            a = a > 0.f ? a : NEG_SLOPE * a;
            s_src[w][i] = s;
            s_w[w][i] = a;
            m = fmaxf(m, a);
        }
        #pragma unroll
        for (int o = 16; o; o >>= 1) m = fmaxf(m, __shfl_xor_sync(0xffffffffu, m, o));
        for (int i = lane; i < deg; i += 32) {
            float ex = __expf(s_w[w][i] - m);
            s_w[w][i] = ex;
            den += ex;
        }
        #pragma unroll
        for (int o = 16; o; o >>= 1) den += __shfl_xor_sync(0xffffffffu, den, o);
        __syncwarp();
        for (int j = 0; j < deg; j++) {
            float wj = s_w[w][j];
            float2 v = h2[(size_t)s_src[w][j] * 32 + lane];
            acc.x += wj * v.x;
            acc.y += wj * v.y;
        }
    } else {
        float m = -INFINITY;
        for (int e = start + lane; e < end; e += 32) {
            float a = as_[ssrc[e]] + adn;
            a = a > 0.f ? a : NEG_SLOPE * a;
            m = fmaxf(m, a);
        }
        #pragma unroll
        for (int o = 16; o; o >>= 1) m = fmaxf(m, __shfl_xor_sync(0xffffffffu, m, o));
        for (int eb = start; eb < end; eb += 32) {
            int e = eb + lane;
            float ex = 0.f; int s = 0;
            if (e < end) {
                s = ssrc[e];
                float a = as_[s] + adn;
                a = a > 0.f ? a : NEG_SLOPE * a;
                ex = __expf(a - m);
            }
            den += ex;
            int cnt = min(32, end - eb);
            for (int j = 0; j < cnt; j++) {
                float wj = __shfl_sync(0xffffffffu, ex, j);
                int sj   = __shfl_sync(0xffffffffu, s, j);
                float2 v = h2[(size_t)sj * 32 + lane];
                acc.x += wj * v.x;
                acc.y += wj * v.y;
            }
        }
        #pragma unroll
        for (int o = 16; o; o >>= 1) den += __shfl_xor_sync(0xffffffffu, den, o);
    }

    float inv = 1.f / den;
    float2 b = ((const float2*)bias)[lane];
    float2 o2 = make_float2(acc.x * inv + b.x, acc.y * inv + b.y);
    ((float2*)out)[(size_t)node * 32 + lane] = o2;
    if (vntmp) {
        int blk = hb[node];
        atomicAdd(&vntmp[blk * H + lane * 2],     o2.x);
        atomicAdd(&vntmp[blk * H + lane * 2 + 1], o2.y);
    }
}

// ---------------- vn update: direct += seg + root; root += colsum(direct) ----------------
__global__ __launch_bounds__(1024) void k_vn_update(float* vn, const float* __restrict__ vn_tmp) {
    __shared__ float red[16 * 64];
    int t = threadIdx.x;
    for (int i = t; i < HNUM * H; i += 1024) {
        vn[i] = vn[i] + vn_tmp[i] + vn[HNUM * H + (i & (H - 1))];
    }
    __syncthreads();
    int col = t & 63, g = t >> 6;
    float s = 0.f;
    for (int r = g * 16; r < g * 16 + 16; r++) s += vn[r * H + col];
    red[g * 64 + col] = s;
    __syncthreads();
    if (t < 64) {
        float tot = 0.f;
        #pragma unroll
        for (int gg = 0; gg < 16; gg++) tot += red[gg * 64 + t];
        vn[HNUM * H + t] += tot;
    }
}

// ---------------- both vn MLPs in one kernel; rows stay in smem ----------------
__global__ __launch_bounds__(256) void k_mlp2(
    float* vn, const float* __restrict__ mw1, const float* __restrict__ mb1,
    const float* __restrict__ mw2, const float* __restrict__ mb2, int rows) {
    __shared__ __align__(16) float sW[H * H];
    __shared__ float sV[64 * 65];
    int t = threadIdx.x;
    int r0 = blockIdx.x * 64;
    for (int i = t; i < 64 * H; i += 256) {
        int r = i >> 6, c = i & 63;
        sV[r * 65 + c] = (r0 + r < rows) ? vn[(r0 + r) * H + c] : 0.f;
    }
    int ty = t >> 4, tx = t & 15;
    for (int m = 0; m < 2; m++) {
        const float* w1 = mw1 + m * H * H;
        const float* b1 = mb1 + m * H;
        const float* w2 = mw2 + m * H * H;
        const float* b2 = mb2 + m * H;
        for (int i = t; i < H * H; i += 256) sW[i] = w1[i];
        __syncthreads();
        float acc[4][4] = {};
        #pragma unroll 8
        for (int k = 0; k < H; k++) {
            float a0 = sV[(ty * 4 + 0) * 65 + k];
            float a1 = sV[(ty * 4 + 1) * 65 + k];
            float a2 = sV[(ty * 4 + 2) * 65 + k];
            float a3 = sV[(ty * 4 + 3) * 65 + k];
            float4 w4 = *(const float4*)&sW[k * H + tx * 4];
            acc[0][0] += a0 * w4.x; acc[0][1] += a0 * w4.y; acc[0][2] += a0 * w4.z; acc[0][3] += a0 * w4.w;
            acc[1][0] += a1 * w4.x; acc[1][1] += a1 * w4.y; acc[1][2] += a1 * w4.z; acc[1][3] += a1 * w4.w;
            acc[2][0] += a2 * w4.x; acc[2][1] += a2 * w4.y; acc[2][2] += a2 * w4.z; acc[2][3] += a2 * w4.w;
            acc[3][0] += a3 * w4.x; acc[3][1] += a3 * w4.y; acc[3][2] += a3 * w4.z; acc[3][3] += a3 * w4.w;
        }
        __syncthreads();
        #pragma unroll
        for (int i = 0; i < 4; i++)
            #pragma unroll
            for (int j = 0; j < 4; j++) {
                float vbl = acc[i][j] + b1[tx * 4 + j];
                sV[(ty * 4 + i) * 65 + tx * 4 + j] = vbl > 0.f ? vbl : 0.f;
            }
        for (int i = t; i < H * H; i += 256) sW[i] = w2[i];
        __syncthreads();
        float acc2[4][4] = {};
        #pragma unroll 8
        for (int k = 0; k < H; k++) {
            float a0 = sV[(ty * 4 + 0) * 65 + k];
            float a1 = sV[(ty * 4 + 1) * 65 + k];
            float a2 = sV[(ty * 4 + 2) * 65 + k];
            float a3 = sV[(ty * 4 + 3) * 65 + k];
            float4 w4 = *(const float4*)&sW[k * H + tx * 4];
            acc2[0][0] += a0 * w4.x; acc2[0][1] += a0 * w4.y; acc2[0][2] += a0 * w4.z; acc2[0][3] += a0 * w4.w;
            acc2[1][0] += a1 * w4.x; acc2[1][1] += a1 * w4.y; acc2[1][2] += a1 * w4.z; acc2[1][3] += a1 * w4.w;
            acc2[2][0] += a2 * w4.x; acc2[2][1] += a2 * w4.y; acc2[2][2] += a2 * w4.z; acc2[2][3] += a2 * w4.w;
            acc2[3][0] += a3 * w4.x; acc2[3][1] += a3 * w4.y; acc2[3][2] += a3 * w4.z; acc2[3][3] += a3 * w4.w;
        }
        __syncthreads();
        #pragma unroll
        for (int i = 0; i < 4; i++)
            #pragma unroll
            for (int j = 0; j < 4; j++) {
                float vbl = acc2[i][j] + b2[tx * 4 + j];
                sV[(ty * 4 + i) * 65 + tx * 4 + j] = vbl > 0.f ? vbl : 0.f;
            }
        __syncthreads();
    }
    for (int i = t; i < 64 * H; i += 256) {
        int r = i >> 6, c = i & 63;
        if (r0 + r < rows) vn[(r0 + r) * H + c] = sV[r * 65 + c];
    }
}

// ---------------- host launch ----------------
extern "C" void kernel_launch(void* const* d_in, const int* in_sizes, int n_in,
                              void* d_out, int out_size) {
    const float* x  = (const float*)d_in[0];
    const int*   ei = (const int*)d_in[1];
    const int*   hb = (const int*)d_in[2];
    int base = (n_in >= 18) ? 5 : 4;
    const float* w_in     = (const float*)d_in[base + 0];
    const float* a_src_in = (const float*)d_in[base + 1];
    const float* a_dst_in = (const float*)d_in[base + 2];
    const float* b_in     = (const float*)d_in[base + 3];
    const float* w_l      = (const float*)d_in[base + 4];
    const float* a_src_l  = (const float*)d_in[base + 5];
    const float* a_dst_l  = (const float*)d_in[base + 6];
    const float* b_l      = (const float*)d_in[base + 7];
    const float* mw1      = (const float*)d_in[base + 8];
    const float* mb1      = (const float*)d_in[base + 9];
    const float* mw2      = (const float*)d_in[base + 10];
    const float* mb2      = (const float*)d_in[base + 11];
    const float* vne      = (const float*)d_in[base + 12];

    int N = in_sizes[0] / 3;
    int E = in_sizes[1] / 2;

    float *ph, *pout, *pas, *pad, *pvn, *pvntmp, *puv;
    int *pdeg, *pst, *pen, *pcur, *pssrc, *ptotal;
    cudaGetSymbolAddress((void**)&ph, g_h);
    cudaGetSymbolAddress((void**)&pout, g_out);
    cudaGetSymbolAddress((void**)&pas, g_as);
    cudaGetSymbolAddress((void**)&pad, g_ad);
    cudaGetSymbolAddress((void**)&pdeg, g_deg);
    cudaGetSymbolAddress((void**)&pst, g_st);
    cudaGetSymbolAddress((void**)&pen, g_en);
    cudaGetSymbolAddress((void**)&pcur, g_cur);
    cudaGetSymbolAddress((void**)&pssrc, g_ssrc);
    cudaGetSymbolAddress((void**)&ptotal, g_total);
    cudaGetSymbolAddress((void**)&pvn, g_vn);
    cudaGetSymbolAddress((void**)&pvntmp, g_vntmp);
    cudaGetSymbolAddress((void**)&puv, g_uv);

    int nwarp_blocks = (N + 7) / 8;
    int gemm_blocks  = (N + 63) / 64;
    int setup_blocks = 130 + (N + 255) / 256;

    // 0: setup (uv fold, vn init, vntmp zero, input as/ad)
    k_setup<<<setup_blocks, 256>>>(x, w_in, a_src_in, a_dst_in,
                                   w_l, a_src_l, a_dst_l,
                                   puv, pvn, pvntmp, vne, pas, pad, N);
    // 1-3: CSR build
    k_hist<<<(E + 255) / 256, 256>>>(ei, pdeg, ptotal, E);
    k_alloc<<<(N + 255) / 256, 256>>>(pdeg, pst, pen, pcur, ptotal, N);
    k_scatter<<<(E + N + 255) / 256, 256>>>(ei, pcur, pssrc, E, N);

    // 4: input GAT layer — gathers raw x, applies W_in post-aggregation
    k_gat_in<<<nwarp_blocks, 256>>>(x, pas, pad, pst, pen, pssrc,
                                    w_in, b_in, pout, N);
    // 5-8: l = 0
    k_gemm64<<<gemm_blocks, 256>>>(pout, w_l, puv, puv + H, pvn, hb, ph, pas, pad, N);
    k_gat<<<nwarp_blocks, 256>>>((const float2*)ph, pas, pad, pst, pen, pssrc,
                                 b_l, pout, pvntmp, hb, N);
    k_vn_update<<<1, 1024>>>(pvn, pvntmp);
    k_mlp2<<<(HNUM + 1 + 63) / 64, 256>>>(pvn, mw1, mb1, mw2, mb2, HNUM + 1);

    // 9-10: l = 1 (trailing vn updates are dead code w.r.t. output)
    k_gemm64<<<gemm_blocks, 256>>>(pout, w_l + H * H, puv + 2 * H, puv + 3 * H,
                                   pvn, hb, ph, pas, pad, N);
    k_gat<<<nwarp_blocks, 256>>>((const float2*)ph, pas, pad, pst, pen, pssrc,
                                 b_l + H, (float*)d_out, nullptr, nullptr, N);
}